// round 17
// baseline (speedup 1.0000x reference)
#include <cuda_runtime.h>
#include <cuda_fp16.h>
#include <cuda_fp8.h>
#include <cstdint>

#define NPTS   100000
#define BATCH  16
#define MNB    9
#define NSLOTS (NPTS * 3)              /* per-batch floats, divisible by 4 */
#define TP     128                     /* points per k_diff tile           */
#define QB     (TP * 3 / 4)            /* 96 float4 slots per batch        */
#define ROWB   64                      /* padded fp8 row bytes (48B data)  */
#define FP8_SCALE 32.0f
#define INV_COUNT (1.0f / (float)(BATCH * NPTS * 3))
#define SCALE_INV (INV_COUNT / FP8_SCALE)

/* k_lap: 3 lanes/point, 10 pts/warp, 16 warps/block -> 160 pts/block */
#define LAP_WARPS   16
#define PTS_PER_WARP 10
#define PTS_PER_BLK (LAP_WARPS * PTS_PER_WARP)   /* 160  */
#define LAP_BLOCKS  (NPTS / PTS_PER_BLK)         /* 625, exact */

// Scratch: d = (gt - pr) * 32 in fp8 e4m3. Row n at byte n*64; bytes
// [0,48) hold value (c,b) at byte c*16+b; [48,64) pad (never read).
// Row NPTS is all-zero (reference's zero-padded pc_ext row).
__device__ __align__(128) unsigned char g_dt[(NPTS + 1) * ROWB];

// ---------------------------------------------------------------------------
// Kernel 1: diff + transpose (B,N,3) -> fp8 rows. Wide STG.128 stores.
// Signals PDL dependents after its stores so k_lap can ramp up early.
// ---------------------------------------------------------------------------
__global__ void k_diff(const float* __restrict__ gt, const float* __restrict__ pr,
                       float* __restrict__ out) {
    if (blockIdx.x == 0) {
        if (threadIdx.x == 0) out[0] = 0.0f;
        if (threadIdx.x < 4)   // zero row NPTS (64B)
            ((uint4*)(g_dt + (size_t)NPTS * ROWB))[threadIdx.x] =
                make_uint4(0u, 0u, 0u, 0u);
    }

    __shared__ float4 s4[QB * 16];     // 24KB
    const float* sf = (const float*)s4;

    int n0 = blockIdx.x * TP;
    int slot0 = n0 * 3;

    // Load phase: i = b*QB + q; coalesced float4 reads per batch stream;
    // smem bank = 4*((b&7)^(q&7)) -> conflict-free.
    for (int i = threadIdx.x; i < 16 * QB; i += 256) {
        int b = i / QB;
        int q = i - b * QB;
        int slot = slot0 + q * 4;
        float4 v = make_float4(0.f, 0.f, 0.f, 0.f);
        if (slot < NSLOTS) {
            float4 g = *(const float4*)(gt + (size_t)b * NSLOTS + slot);
            float4 p = *(const float4*)(pr + (size_t)b * NSLOTS + slot);
            v = make_float4(g.x - p.x, g.y - p.y, g.z - p.z, g.w - p.w);
        }
        s4[q * 16 + (b ^ (q & 15))] = v;
    }
    __syncthreads();

    // Store phase: one uint4 per (point, component) = 16 fp8 batch values.
    int valid = NPTS - n0;
    if (valid > TP) valid = TP;
    int total = valid * 3;
    for (int j = threadIdx.x; j < total; j += 256) {
        int p = j / 3;
        int c = j - 3 * p;
        int r = p * 3 + c;             // slot within tile
        int q = r >> 2;
        int cmp = r & 3;
        uint32_t wds[4];
        #pragma unroll
        for (int bq = 0; bq < 4; bq++) {
            int b0 = bq << 2;
            float f0 = sf[4 * (q * 16 + ((b0 + 0) ^ (q & 15))) + cmp] * FP8_SCALE;
            float f1 = sf[4 * (q * 16 + ((b0 + 1) ^ (q & 15))) + cmp] * FP8_SCALE;
            float f2 = sf[4 * (q * 16 + ((b0 + 2) ^ (q & 15))) + cmp] * FP8_SCALE;
            float f3 = sf[4 * (q * 16 + ((b0 + 3) ^ (q & 15))) + cmp] * FP8_SCALE;
            __nv_fp8x2_storage_t lo =
                __nv_cvt_float2_to_fp8x2(make_float2(f0, f1), __NV_SATFINITE, __NV_E4M3);
            __nv_fp8x2_storage_t hi =
                __nv_cvt_float2_to_fp8x2(make_float2(f2, f3), __NV_SATFINITE, __NV_E4M3);
            wds[bq] = (uint32_t)lo | ((uint32_t)hi << 16);
        }
        *(uint4*)(g_dt + (size_t)(n0 + p) * ROWB + c * 16) =
            make_uint4(wds[0], wds[1], wds[2], wds[3]);
    }

    // PDL: all this block's scratch stores are issued; allow dependents.
    asm volatile("griddepcontrol.launch_dependents;" ::: "memory");
}

// ---------------------------------------------------------------------------
// fp8x2 -> half2 decode
// ---------------------------------------------------------------------------
__device__ __forceinline__ __half2 fp8x2_h2(uint32_t w16) {
    __half2_raw r = __nv_cvt_fp8x2_to_halfraw2((__nv_fp8x2_storage_t)w16, __NV_E4M3);
    return *(__half2*)&r;
}

// ---------------------------------------------------------------------------
// Kernel 2: gather laplacian. 10 points/warp, 3 lanes/point, lane owns one
// 16B chunk (16 fp8) of the 64B row. Intrinsic uint4 gathers (compiler-
// scheduled — measured fastest), fp16 epilogue, PDL-launched.
// ---------------------------------------------------------------------------
__global__ void __launch_bounds__(LAP_WARPS * 32)
k_lap(const int* __restrict__ nb, const float* __restrict__ num,
      float* __restrict__ out) {
    const unsigned FULL = 0xFFFFFFFFu;
    int tid  = threadIdx.x;
    int lane = tid & 31;
    int w    = tid >> 5;
    int g    = lane / 3;                         // point group 0..9 (10 -> idle)
    int s    = lane - g * 3;                     // chunk 0..2
    bool act = lane < 30;
    int n    = blockIdx.x * PTS_PER_BLK + w * PTS_PER_WARP + (act ? g : 0);

    // neighbor ids 1..8 + num: pure input reads, safe before the PDL wait
    int ids[8];
    #pragma unroll
    for (int j = 0; j < 8; j++)
        ids[j] = __ldg(nb + (size_t)n * MNB + 1 + j);   // in [0, NPTS]
    float wnum = __ldg(num + n);

    // PDL: block until k_diff's stores are visible
    asm volatile("griddepcontrol.wait;" ::: "memory");

    const char* base = (const char*)g_dt;
    int coff = s * 16;

    // center: own row (nb[:,0] is arange), coalesced across the warp
    uint4 cv = *(const uint4*)(base + (size_t)n * ROWB + coff);

    // 8 random gathers, unconditional (row NPTS is zero)
    uint4 v[8];
    #pragma unroll
    for (int j = 0; j < 8; j++)
        v[j] = *(const uint4*)(base + (size_t)ids[j] * ROWB + coff);

    // accumulate 16 fp8 positions in 8 independent half2 chains
    __half2 acc[8];
    #pragma unroll
    for (int k = 0; k < 8; k++) acc[k] = __float2half2_rn(0.0f);
    #pragma unroll
    for (int j = 0; j < 8; j++) {
        const uint32_t* wd = (const uint32_t*)&v[j];
        #pragma unroll
        for (int k = 0; k < 4; k++) {
            acc[2 * k]     = __hadd2(acc[2 * k],     fp8x2_h2(wd[k] & 0xFFFFu));
            acc[2 * k + 1] = __hadd2(acc[2 * k + 1], fp8x2_h2(wd[k] >> 16));
        }
    }

    // fp16 epilogue: |center*num - sum| accumulated in half2, one final cvt
    float accw = 0.0f;
    if (act) {
        __half2 wn2 = __float2half2_rn(wnum);
        const uint32_t* cw = (const uint32_t*)&cv;
        __half2 t = __float2half2_rn(0.0f);
        #pragma unroll
        for (int k = 0; k < 4; k++) {
            __half2 clo = fp8x2_h2(cw[k] & 0xFFFFu);
            __half2 chi = fp8x2_h2(cw[k] >> 16);
            t = __hadd2(t, __habs2(__hsub2(__hmul2(clo, wn2), acc[2 * k])));
            t = __hadd2(t, __habs2(__hsub2(__hmul2(chi, wn2), acc[2 * k + 1])));
        }
        float2 tf = __half22float2(t);
        accw = tf.x + tf.y;
    }

    // warp reduce (fixed order), block reduce, one atomic per block
    #pragma unroll
    for (int off = 16; off > 0; off >>= 1)
        accw += __shfl_down_sync(FULL, accw, off);

    __shared__ float ws[LAP_WARPS];
    if (lane == 0) ws[w] = accw;
    __syncthreads();
    if (tid < LAP_WARPS) {
        float x = ws[tid];
        #pragma unroll
        for (int off = LAP_WARPS / 2; off > 0; off >>= 1)
            x += __shfl_down_sync(0xFFFFu, x, off);
        if (tid == 0)
            atomicAdd(out, x * SCALE_INV);
    }
}

// ---------------------------------------------------------------------------
extern "C" void kernel_launch(void* const* d_in, const int* in_sizes, int n_in,
                              void* d_out, int out_size) {
    const float* gt  = (const float*)d_in[0];   // gt_pc        (B,N,3) f32
    const float* pr  = (const float*)d_in[1];   // predict_pc   (B,N,3) f32
    const int*   nb  = (const int*)  d_in[2];   // neighbor ids (N,9)   i32
    const float* num = (const float*)d_in[3];   // neighbor_num (N,)    f32
    float* out = (float*)d_out;

    int nblk1 = (NPTS + TP - 1) / TP;           // 782
    k_diff<<<nblk1, 256>>>(gt, pr, out);

    // k_lap with programmatic dependent launch: overlaps its prologue with
    // k_diff's tail; griddepcontrol.wait guards the g_dt reads.
    cudaLaunchConfig_t cfg = {};
    cfg.gridDim  = dim3(LAP_BLOCKS);
    cfg.blockDim = dim3(LAP_WARPS * 32);
    cfg.dynamicSmemBytes = 0;
    cfg.stream = 0;                              // legacy default (capture) stream
    cudaLaunchAttribute attr[1];
    attr[0].id = cudaLaunchAttributeProgrammaticStreamSerialization;
    attr[0].val.programmaticStreamSerializationAllowed = 1;
    cfg.attrs = attr;
    cfg.numAttrs = 1;
    cudaLaunchKernelEx(&cfg, k_lap, nb, num, out);
}